// round 1
// baseline (speedup 1.0000x reference)
#include <cuda_runtime.h>
#include <cuda_bf16.h>

// Problem constants (match reference setup_inputs)
#define NN     50000
#define IN_C   256
#define HID_C  128
#define OUT_C  64

// ---------------- scratch (device globals; no allocs allowed) ----------------
__device__ __align__(16) float g_deg [NN];
__device__ __align__(16) float g_dinv[NN];
__device__ __align__(16) float g_h   [NN * HID_C];   // x @ W1
__device__ __align__(16) float g_agg [NN * HID_C];   // aggregated layer-1 (pre-relu)
__device__ __align__(16) float g_z   [NN * OUT_C];   // relu(agg) @ W2

// ---------------- degree / norm ----------------
__global__ void zero_deg_kernel(float* deg, int n) {
    int i = blockIdx.x * blockDim.x + threadIdx.x;
    if (i < n) deg[i] = 0.0f;
}

__global__ void count_deg_kernel(const int* __restrict__ dst, float* __restrict__ deg, int E) {
    int e = blockIdx.x * blockDim.x + threadIdx.x;
    if (e < E) atomicAdd(&deg[dst[e]], 1.0f);
}

__global__ void dinv_kernel(const float* __restrict__ deg, float* __restrict__ dinv, int n) {
    int i = blockIdx.x * blockDim.x + threadIdx.x;
    if (i < n) dinv[i] = rsqrtf(deg[i] + 1.0f);   // +1 = self loop; always > 0
}

// ---------------- SGEMM: C[M,Nc] = A[M,K] @ B[K,Nc], optional relu on A loads --------
// BM=64, BN=64, BK=16, TM=TN=4, 256 threads.
template<bool RELU>
__global__ void sgemm_kernel(const float* __restrict__ A, const float* __restrict__ B,
                             float* __restrict__ C, int M, int K, int Nc) {
    __shared__ float As[16][64];   // [k][m]
    __shared__ float Bs[16][64];   // [k][n]

    const int tid = threadIdx.x;
    const int tx  = tid & 15;      // n-group
    const int ty  = tid >> 4;      // m-group
    const int row0 = blockIdx.x * 64;
    const int col0 = blockIdx.y * 64;

    const int a_row = tid >> 2;          // 0..63
    const int a_k   = (tid & 3) * 4;     // 0,4,8,12
    const int b_k   = tid >> 4;          // 0..15
    const int b_col = (tid & 15) * 4;    // 0..60

    float acc[4][4];
    #pragma unroll
    for (int i = 0; i < 4; i++)
        #pragma unroll
        for (int j = 0; j < 4; j++) acc[i][j] = 0.0f;

    for (int k0 = 0; k0 < K; k0 += 16) {
        float4 av = make_float4(0.f, 0.f, 0.f, 0.f);
        int ar = row0 + a_row;
        if (ar < M)
            av = *reinterpret_cast<const float4*>(A + (long long)ar * K + k0 + a_k);
        if (RELU) {
            av.x = fmaxf(av.x, 0.f); av.y = fmaxf(av.y, 0.f);
            av.z = fmaxf(av.z, 0.f); av.w = fmaxf(av.w, 0.f);
        }
        As[a_k + 0][a_row] = av.x;
        As[a_k + 1][a_row] = av.y;
        As[a_k + 2][a_row] = av.z;
        As[a_k + 3][a_row] = av.w;

        float4 bv = *reinterpret_cast<const float4*>(B + (long long)(k0 + b_k) * Nc + col0 + b_col);
        *reinterpret_cast<float4*>(&Bs[b_k][b_col]) = bv;

        __syncthreads();

        #pragma unroll
        for (int k = 0; k < 16; k++) {
            float a[4], b[4];
            #pragma unroll
            for (int i = 0; i < 4; i++) a[i] = As[k][ty * 4 + i];
            #pragma unroll
            for (int j = 0; j < 4; j++) b[j] = Bs[k][tx * 4 + j];
            #pragma unroll
            for (int i = 0; i < 4; i++)
                #pragma unroll
                for (int j = 0; j < 4; j++)
                    acc[i][j] = fmaf(a[i], b[j], acc[i][j]);
        }
        __syncthreads();
    }

    #pragma unroll
    for (int i = 0; i < 4; i++) {
        int r = row0 + ty * 4 + i;
        if (r < M) {
            float4 v = make_float4(acc[i][0], acc[i][1], acc[i][2], acc[i][3]);
            *reinterpret_cast<float4*>(C + (long long)r * Nc + col0 + tx * 4) = v;
        }
    }
}

// ---------------- per-node init: agg = bias + dinv[i]^2 * h (self loop) -------------
template<int C>
__global__ void init_self_kernel(const float* __restrict__ h, const float* __restrict__ dinv,
                                 const float* __restrict__ bias, float* __restrict__ agg, int n) {
    long long idx = (long long)blockIdx.x * blockDim.x + threadIdx.x;
    long long total = (long long)n * C;
    if (idx >= total) return;
    int i = (int)(idx / C);
    int c = (int)(idx % C);
    float di = dinv[i];
    agg[idx] = bias[c] + di * di * h[idx];
}

// ---------------- edge scatter: agg[dst] += dinv[src]*dinv[dst] * h[src] ------------
// One float4 channel-chunk per thread; consecutive threads cover one edge's channels.
template<int LOGC4, int C>
__global__ void scatter_kernel(const float* __restrict__ h,
                               const int* __restrict__ src, const int* __restrict__ dst,
                               const float* __restrict__ dinv,
                               float* __restrict__ agg, int E) {
    const int C4 = 1 << LOGC4;                       // chunks of 4 floats per edge
    long long idx = (long long)blockIdx.x * blockDim.x + threadIdx.x;
    long long total = (long long)E << LOGC4;
    if (idx >= total) return;
    int e = (int)(idx >> LOGC4);
    int c = (int)(idx & (C4 - 1)) * 4;

    int s = src[e];
    int d = dst[e];
    float nrm = dinv[s] * dinv[d];

    float4 v = *reinterpret_cast<const float4*>(h + (long long)s * C + c);
    float* out = agg + (long long)d * C + c;
    atomicAdd(out + 0, v.x * nrm);
    atomicAdd(out + 1, v.y * nrm);
    atomicAdd(out + 2, v.z * nrm);
    atomicAdd(out + 3, v.w * nrm);
}

// ---------------- launch ----------------
extern "C" void kernel_launch(void* const* d_in, const int* in_sizes, int n_in,
                              void* d_out, int out_size) {
    const float* x  = (const float*)d_in[0];
    const int*   ei = (const int*)  d_in[1];
    const float* W1 = (const float*)d_in[2];
    const float* b1 = (const float*)d_in[3];
    const float* W2 = (const float*)d_in[4];
    const float* b2 = (const float*)d_in[5];
    float* out = (float*)d_out;

    const int E = in_sizes[1] / 2;
    const int* src = ei;
    const int* dst = ei + E;

    float *deg, *dinv, *h, *agg, *z;
    cudaGetSymbolAddress((void**)&deg,  g_deg);
    cudaGetSymbolAddress((void**)&dinv, g_dinv);
    cudaGetSymbolAddress((void**)&h,    g_h);
    cudaGetSymbolAddress((void**)&agg,  g_agg);
    cudaGetSymbolAddress((void**)&z,    g_z);

    // 1) normalization coefficients
    zero_deg_kernel<<<(NN + 255) / 256, 256>>>(deg, NN);
    count_deg_kernel<<<(E + 255) / 256, 256>>>(dst, deg, E);
    dinv_kernel<<<(NN + 255) / 256, 256>>>(deg, dinv, NN);

    // 2) layer 1: h = x @ W1
    {
        dim3 grid((NN + 63) / 64, HID_C / 64);
        sgemm_kernel<false><<<grid, 256>>>(x, W1, h, NN, IN_C, HID_C);
    }
    // 3) agg = b1 + selfloop + sum over edges
    {
        long long total = (long long)NN * HID_C;
        init_self_kernel<HID_C><<<(int)((total + 255) / 256), 256>>>(h, dinv, b1, agg, NN);
        long long etotal = (long long)E * (HID_C / 4);
        scatter_kernel<5, HID_C><<<(int)((etotal + 255) / 256), 256>>>(h, src, dst, dinv, agg, E);
    }
    // 4) layer 2 GEMM with fused relu on A: z = relu(agg) @ W2
    {
        dim3 grid((NN + 63) / 64, OUT_C / 64);
        sgemm_kernel<true><<<grid, 256>>>(agg, W2, z, NN, HID_C, OUT_C);
    }
    // 5) out = b2 + selfloop + sum over edges
    {
        long long total = (long long)NN * OUT_C;
        init_self_kernel<OUT_C><<<(int)((total + 255) / 256), 256>>>(z, dinv, b2, out, NN);
        long long etotal = (long long)E * (OUT_C / 4);
        scatter_kernel<4, OUT_C><<<(int)((etotal + 255) / 256), 256>>>(z, src, dst, dinv, out, E);
    }
}

// round 2
// speedup vs baseline: 1.5963x; 1.5963x over previous
#include <cuda_runtime.h>
#include <cuda_bf16.h>

// Problem constants (match reference setup_inputs)
#define NN     50000
#define IN_C   256
#define HID_C  128
#define OUT_C  64

// ---------------- scratch (device globals; no allocs allowed) ----------------
__device__ __align__(16) float g_deg [NN];
__device__ __align__(16) float g_dinv[NN];
__device__ __align__(16) float g_h   [NN * HID_C];   // x @ W1
__device__ __align__(16) float g_agg [NN * HID_C];   // aggregated layer-1 (pre-relu)
__device__ __align__(16) float g_z   [NN * OUT_C];   // relu(agg) @ W2

// ---------------- degree / norm ----------------
__global__ void zero_deg_kernel(float* deg, int n) {
    int i = blockIdx.x * blockDim.x + threadIdx.x;
    if (i < n) deg[i] = 0.0f;
}

__global__ void count_deg_kernel(const int* __restrict__ dst, float* __restrict__ deg, int E) {
    int e = blockIdx.x * blockDim.x + threadIdx.x;
    if (e < E) atomicAdd(&deg[dst[e]], 1.0f);
}

__global__ void dinv_kernel(const float* __restrict__ deg, float* __restrict__ dinv, int n) {
    int i = blockIdx.x * blockDim.x + threadIdx.x;
    if (i < n) dinv[i] = rsqrtf(deg[i] + 1.0f);   // +1 = self loop; always > 0
}

// ---------------- SGEMM: C[M,Nc] = A[M,K] @ B[K,Nc], optional relu on A loads --------
// BM=64, BN=64, BK=16, TM=TN=4, 256 threads. Vectorized LDS.128 fragment reads.
template<bool RELU>
__global__ void sgemm_kernel(const float* __restrict__ A, const float* __restrict__ B,
                             float* __restrict__ C, int M, int K, int Nc) {
    __shared__ __align__(16) float As[16][64];   // [k][m]
    __shared__ __align__(16) float Bs[16][64];   // [k][n]

    const int tid = threadIdx.x;
    const int tx  = tid & 15;      // n-group
    const int ty  = tid >> 4;      // m-group
    const int row0 = blockIdx.x * 64;
    const int col0 = blockIdx.y * 64;

    const int a_row = tid >> 2;          // 0..63
    const int a_k   = (tid & 3) * 4;     // 0,4,8,12
    const int b_k   = tid >> 4;          // 0..15
    const int b_col = (tid & 15) * 4;    // 0..60

    float acc[4][4];
    #pragma unroll
    for (int i = 0; i < 4; i++)
        #pragma unroll
        for (int j = 0; j < 4; j++) acc[i][j] = 0.0f;

    for (int k0 = 0; k0 < K; k0 += 16) {
        float4 av = make_float4(0.f, 0.f, 0.f, 0.f);
        int ar = row0 + a_row;
        if (ar < M)
            av = *reinterpret_cast<const float4*>(A + (long long)ar * K + k0 + a_k);
        if (RELU) {
            av.x = fmaxf(av.x, 0.f); av.y = fmaxf(av.y, 0.f);
            av.z = fmaxf(av.z, 0.f); av.w = fmaxf(av.w, 0.f);
        }
        As[a_k + 0][a_row] = av.x;
        As[a_k + 1][a_row] = av.y;
        As[a_k + 2][a_row] = av.z;
        As[a_k + 3][a_row] = av.w;

        float4 bv = *reinterpret_cast<const float4*>(B + (long long)(k0 + b_k) * Nc + col0 + b_col);
        *reinterpret_cast<float4*>(&Bs[b_k][b_col]) = bv;

        __syncthreads();

        #pragma unroll
        for (int k = 0; k < 16; k++) {
            // 16B-aligned vector reads: A fragment broadcast within warp,
            // B fragment conflict-free across 16 tx groups.
            float4 a4 = *reinterpret_cast<const float4*>(&As[k][ty * 4]);
            float4 b4 = *reinterpret_cast<const float4*>(&Bs[k][tx * 4]);
            float a[4] = {a4.x, a4.y, a4.z, a4.w};
            float b[4] = {b4.x, b4.y, b4.z, b4.w};
            #pragma unroll
            for (int i = 0; i < 4; i++)
                #pragma unroll
                for (int j = 0; j < 4; j++)
                    acc[i][j] = fmaf(a[i], b[j], acc[i][j]);
        }
        __syncthreads();
    }

    #pragma unroll
    for (int i = 0; i < 4; i++) {
        int r = row0 + ty * 4 + i;
        if (r < M) {
            float4 v = make_float4(acc[i][0], acc[i][1], acc[i][2], acc[i][3]);
            *reinterpret_cast<float4*>(C + (long long)r * Nc + col0 + tx * 4) = v;
        }
    }
}

// ---------------- per-node init: agg = bias + dinv[i]^2 * h (self loop) -------------
template<int C>
__global__ void init_self_kernel(const float* __restrict__ h, const float* __restrict__ dinv,
                                 const float* __restrict__ bias, float* __restrict__ agg, int n) {
    long long idx = (long long)blockIdx.x * blockDim.x + threadIdx.x;
    long long total = (long long)n * C;
    if (idx >= total) return;
    int i = (int)(idx / C);
    int c = (int)(idx % C);
    float di = dinv[i];
    agg[idx] = bias[c] + di * di * h[idx];
}

// ---------------- edge scatter: agg[dst] += dinv[src]*dinv[dst] * h[src] ------------
// One float4 channel-chunk per thread; vector REDG.128 atomics (sm_90+).
template<int LOGC4, int C>
__global__ void scatter_kernel(const float* __restrict__ h,
                               const int* __restrict__ src, const int* __restrict__ dst,
                               const float* __restrict__ dinv,
                               float* __restrict__ agg, int E) {
    const int C4 = 1 << LOGC4;                       // chunks of 4 floats per edge
    long long idx = (long long)blockIdx.x * blockDim.x + threadIdx.x;
    long long total = (long long)E << LOGC4;
    if (idx >= total) return;
    int e = (int)(idx >> LOGC4);
    int c = (int)(idx & (C4 - 1)) * 4;

    int s = src[e];
    int d = dst[e];
    float nrm = dinv[s] * dinv[d];

    float4 v = *reinterpret_cast<const float4*>(h + (long long)s * C + c);
    float4 w = make_float4(v.x * nrm, v.y * nrm, v.z * nrm, v.w * nrm);
    atomicAdd(reinterpret_cast<float4*>(agg + (long long)d * C + c), w);
}

// ---------------- launch ----------------
extern "C" void kernel_launch(void* const* d_in, const int* in_sizes, int n_in,
                              void* d_out, int out_size) {
    const float* x  = (const float*)d_in[0];
    const int*   ei = (const int*)  d_in[1];
    const float* W1 = (const float*)d_in[2];
    const float* b1 = (const float*)d_in[3];
    const float* W2 = (const float*)d_in[4];
    const float* b2 = (const float*)d_in[5];
    float* out = (float*)d_out;

    const int E = in_sizes[1] / 2;
    const int* src = ei;
    const int* dst = ei + E;

    float *deg, *dinv, *h, *agg, *z;
    cudaGetSymbolAddress((void**)&deg,  g_deg);
    cudaGetSymbolAddress((void**)&dinv, g_dinv);
    cudaGetSymbolAddress((void**)&h,    g_h);
    cudaGetSymbolAddress((void**)&agg,  g_agg);
    cudaGetSymbolAddress((void**)&z,    g_z);

    // 1) normalization coefficients
    zero_deg_kernel<<<(NN + 255) / 256, 256>>>(deg, NN);
    count_deg_kernel<<<(E + 255) / 256, 256>>>(dst, deg, E);
    dinv_kernel<<<(NN + 255) / 256, 256>>>(deg, dinv, NN);

    // 2) layer 1: h = x @ W1
    {
        dim3 grid((NN + 63) / 64, HID_C / 64);
        sgemm_kernel<false><<<grid, 256>>>(x, W1, h, NN, IN_C, HID_C);
    }
    // 3) agg = b1 + selfloop + sum over edges
    {
        long long total = (long long)NN * HID_C;
        init_self_kernel<HID_C><<<(int)((total + 255) / 256), 256>>>(h, dinv, b1, agg, NN);
        long long etotal = (long long)E * (HID_C / 4);
        scatter_kernel<5, HID_C><<<(int)((etotal + 255) / 256), 256>>>(h, src, dst, dinv, agg, E);
    }
    // 4) layer 2 GEMM with fused relu on A: z = relu(agg) @ W2
    {
        dim3 grid((NN + 63) / 64, OUT_C / 64);
        sgemm_kernel<true><<<grid, 256>>>(agg, W2, z, NN, HID_C, OUT_C);
    }
    // 5) out = b2 + selfloop + sum over edges
    {
        long long total = (long long)NN * OUT_C;
        init_self_kernel<OUT_C><<<(int)((total + 255) / 256), 256>>>(z, dinv, b2, out, NN);
        long long etotal = (long long)E * (OUT_C / 4);
        scatter_kernel<4, OUT_C><<<(int)((etotal + 255) / 256), 256>>>(z, src, dst, dinv, out, E);
    }
}